// round 8
// baseline (speedup 1.0000x reference)
#include <cuda_runtime.h>
#include <cstdint>

// out = X * W[idx][0] + Y * W[idx][1], idx = reward[b,s] in {0,1}
// X,Y: (4,4096,2048) fp32; reward: (4,4096,1) int32; W: (2,2) fp32.
// HBM-bound blend. Persistent grid-stride: 1184 CTAs (148 SMs x occ 8),
// each CTA loops over rows. Inner body = R6 winner: one row per iteration,
// 2 float4/thread at stride 256 (coalesced 512B wavefronts, MLP=4),
// default cache policy (evict-first hints regressed in R7).

__global__ __launch_bounds__(256)
void blend_kernel_pers(const float4* __restrict__ X,
                       const float4* __restrict__ Y,
                       const int* __restrict__ reward,
                       const float* __restrict__ W,
                       float4* __restrict__ out,
                       int nrows)
{
    // Cache both W rows once per thread (4 floats, L1-resident).
    float a_tab0 = W[0], b_tab0 = W[1];
    float a_tab1 = W[2], b_tab1 = W[3];

    for (int row = blockIdx.x; row < nrows; row += gridDim.x) {
        int base = row * 512 + threadIdx.x;

        int r = reward[row];                 // uniform across block
        float a = (r != 0) ? a_tab1 : a_tab0;
        float b = (r != 0) ? b_tab1 : b_tab0;

        // Front-batch 4 global loads (MLP=4).
        float4 x0 = X[base];
        float4 x1 = X[base + 256];
        float4 y0 = Y[base];
        float4 y1 = Y[base + 256];

        float4 o0, o1;
        o0.x = fmaf(x0.x, a, y0.x * b);
        o0.y = fmaf(x0.y, a, y0.y * b);
        o0.z = fmaf(x0.z, a, y0.z * b);
        o0.w = fmaf(x0.w, a, y0.w * b);
        o1.x = fmaf(x1.x, a, y1.x * b);
        o1.y = fmaf(x1.y, a, y1.y * b);
        o1.z = fmaf(x1.z, a, y1.z * b);
        o1.w = fmaf(x1.w, a, y1.w * b);

        out[base]       = o0;
        out[base + 256] = o1;
    }
}

extern "C" void kernel_launch(void* const* d_in, const int* in_sizes, int n_in,
                              void* d_out, int out_size)
{
    const float4* X      = (const float4*)d_in[0];
    const float4* Y      = (const float4*)d_in[1];
    const int*    reward = (const int*)d_in[2];
    const float*  W      = (const float*)d_in[3];
    float4*       out    = (float4*)d_out;

    int n     = out_size;       // 4*4096*2048 = 33554432 fp32
    int nrows = n / 2048;       // 16384 rows

    // Persistent: fill the chip exactly (152 SMs on GB300; 148 on B300 —
    // use 148*8, still a full integer multiple of waves either way).
    int blocks = 1184;
    blend_kernel_pers<<<blocks, 256>>>(X, Y, reward, W, out, nrows);
}

// round 9
// speedup vs baseline: 1.0623x; 1.0623x over previous
#include <cuda_runtime.h>
#include <cstdint>

// out = X * W[idx][0] + Y * W[idx][1], idx = reward[b,s] in {0,1}
// X,Y: (4,4096,2048) fp32; reward: (4,4096,1) int32; W: (2,2) fp32.
// HBM-bound blend. FINAL (R6 winner): one block = one (b,s) row = 512
// contiguous float4. 2 float4/thread at stride 256 -> fully coalesced 512B
// warp wavefronts, MLP=4 front-batched loads/thread, single uniform reward
// load per block, default cache policy, flat 16384-CTA grid.
// Measured: 52.1us kernel, 6757 GB/s (84.5% of spec HBM).
// Rejected by experiment: MLP=8 (L1tex queue contention), __ldcs/__stcs
// (hurt DRAM write coalescing), persistent grid (loop serialization).

__global__ __launch_bounds__(256)
void blend_kernel_row(const float4* __restrict__ X,
                      const float4* __restrict__ Y,
                      const int* __restrict__ reward,
                      const float* __restrict__ W,
                      float4* __restrict__ out)
{
    int base = blockIdx.x * 512 + threadIdx.x;   // row = blockIdx.x

    int idx = (reward[blockIdx.x] != 0) ? 1 : 0; // uniform across block
    float a = W[2 * idx];
    float b = W[2 * idx + 1];

    // Front-batch 4 global loads (MLP=4).
    float4 x0 = X[base];
    float4 x1 = X[base + 256];
    float4 y0 = Y[base];
    float4 y1 = Y[base + 256];

    float4 o0, o1;
    o0.x = fmaf(x0.x, a, y0.x * b);
    o0.y = fmaf(x0.y, a, y0.y * b);
    o0.z = fmaf(x0.z, a, y0.z * b);
    o0.w = fmaf(x0.w, a, y0.w * b);
    o1.x = fmaf(x1.x, a, y1.x * b);
    o1.y = fmaf(x1.y, a, y1.y * b);
    o1.z = fmaf(x1.z, a, y1.z * b);
    o1.w = fmaf(x1.w, a, y1.w * b);

    out[base]       = o0;
    out[base + 256] = o1;
}

extern "C" void kernel_launch(void* const* d_in, const int* in_sizes, int n_in,
                              void* d_out, int out_size)
{
    const float4* X      = (const float4*)d_in[0];
    const float4* Y      = (const float4*)d_in[1];
    const int*    reward = (const int*)d_in[2];
    const float*  W      = (const float*)d_in[3];
    float4*       out    = (float4*)d_out;

    int n  = out_size;          // 4*4096*2048 = 33554432 fp32
    int n4 = n / 4;             // 8388608 float4
    int blocks = n4 / 512;      // 16384 blocks, one row each (exact)

    blend_kernel_row<<<blocks, 256>>>(X, Y, reward, W, out);
}

// round 10
// speedup vs baseline: 1.0667x; 1.0041x over previous
#include <cuda_runtime.h>
#include <cstdint>

// out = X * W[idx][0] + Y * W[idx][1], idx = reward[b,s] in {0,1}
// X,Y: (4,4096,2048) fp32; reward: (4,4096,1) int32; W: (2,2) fp32.
// HBM-bound blend. R6 structure (proven best): one block = one row = 512
// contiguous float4, 2 float4/thread at stride 256, MLP=4, flat 16384 grid.
// This round's single variable: __ldlu (last-use) on the X/Y streams only —
// frees L2 sectors right after delivery, leaving more L2 staging capacity
// for the store stream. Stores stay default policy (evict-first stores
// regressed in R7).

__global__ __launch_bounds__(256)
void blend_kernel_rowlu(const float4* __restrict__ X,
                        const float4* __restrict__ Y,
                        const int* __restrict__ reward,
                        const float* __restrict__ W,
                        float4* __restrict__ out)
{
    int base = blockIdx.x * 512 + threadIdx.x;   // row = blockIdx.x

    int idx = (reward[blockIdx.x] != 0) ? 1 : 0; // uniform across block
    float a = W[2 * idx];
    float b = W[2 * idx + 1];

    // Front-batch 4 global loads (MLP=4), last-use policy on streams.
    float4 x0 = __ldlu(&X[base]);
    float4 x1 = __ldlu(&X[base + 256]);
    float4 y0 = __ldlu(&Y[base]);
    float4 y1 = __ldlu(&Y[base + 256]);

    float4 o0, o1;
    o0.x = fmaf(x0.x, a, y0.x * b);
    o0.y = fmaf(x0.y, a, y0.y * b);
    o0.z = fmaf(x0.z, a, y0.z * b);
    o0.w = fmaf(x0.w, a, y0.w * b);
    o1.x = fmaf(x1.x, a, y1.x * b);
    o1.y = fmaf(x1.y, a, y1.y * b);
    o1.z = fmaf(x1.z, a, y1.z * b);
    o1.w = fmaf(x1.w, a, y1.w * b);

    out[base]       = o0;   // default store policy
    out[base + 256] = o1;
}

extern "C" void kernel_launch(void* const* d_in, const int* in_sizes, int n_in,
                              void* d_out, int out_size)
{
    const float4* X      = (const float4*)d_in[0];
    const float4* Y      = (const float4*)d_in[1];
    const int*    reward = (const int*)d_in[2];
    const float*  W      = (const float*)d_in[3];
    float4*       out    = (float4*)d_out;

    int n  = out_size;          // 4*4096*2048 = 33554432 fp32
    int n4 = n / 4;             // 8388608 float4
    int blocks = n4 / 512;      // 16384 blocks, one row each (exact)

    blend_kernel_rowlu<<<blocks, 256>>>(X, Y, reward, W, out);
}